// round 15
// baseline (speedup 1.0000x reference)
#include <cuda_runtime.h>
#include <cuda_fp16.h>
#include <cstdint>

#define DHID   128
#define NB     4
#define NN_MAX 100096
#define NE_MAX 800000
#define NBKT_N 102400
#define NSCAN_BLK (NBKT_N / 1024)

// Scratch
__device__ __half   g_x[(size_t)NN_MAX * DHID];         // fp16 node feats (25.6 MB)
__device__ __half   g_y[(size_t)NN_MAX * NB * DHID];    // fp16 aggregated, deg-scaled (102 MB)
__device__ __half   g_wt2[DHID * NB * DHID];            // Wt[o][b*128+i] fp16
__device__ uint32_t g_hist[NBKT_N];
__device__ uint32_t g_bsum[128];
__device__ uint2    g_edges2[NE_MAX];                   // dst-sorted {src|rel<<20, norm}

#define KP 136

// ---------------------------------------------------------------------------
// Fused prep: weight transpose + x fp16 conversion + hist zero (R12 exact)
// ---------------------------------------------------------------------------
__global__ void rgcn_prep_all(const float* __restrict__ weight,
                              const int*   __restrict__ h,
                              const float* __restrict__ emb,
                              int n_nodes)
{
    int idx = blockIdx.x * blockDim.x + threadIdx.x;

    if (idx < NB * DHID * DHID) {
        int b = idx >> 14;
        int i = (idx >> 7) & 127;
        int o = idx & 127;
        g_wt2[o * (NB * DHID) + b * DHID + i] = __float2half_rn(weight[idx]);
    }
    if (idx < NBKT_N) g_hist[idx] = 0u;

    if (idx < n_nodes * 32) {
        int n  = idx >> 5;
        int qc = (idx & 31) * 4;
        int hn = __ldg(h + n);
        float4 v = *reinterpret_cast<const float4*>(emb + (size_t)hn * DHID + qc);
        __half2 p0 = __floats2half2_rn(v.x, v.y);
        __half2 p1 = __floats2half2_rn(v.z, v.w);
        uint2 pk;
        pk.x = *reinterpret_cast<uint32_t*>(&p0);
        pk.y = *reinterpret_cast<uint32_t*>(&p1);
        *reinterpret_cast<uint2*>(g_x + (size_t)n * DHID + qc) = pk;
    }
}

// ---------------------------------------------------------------------------
// dst counting sort (R12 exact: scalar hist, 2-level scan, scatter)
// ---------------------------------------------------------------------------
__global__ void rgcn_hist_kernel(const int* __restrict__ dst, int n_edges)
{
    int e = blockIdx.x * blockDim.x + threadIdx.x;
    if (e >= n_edges) return;
    atomicAdd(&g_hist[(unsigned)dst[e]], 1u);
}

__global__ __launch_bounds__(1024) void rgcn_scan_local()
{
    __shared__ uint32_t sh[1024];
    int t = threadIdx.x;
    int i = blockIdx.x * 1024 + t;
    uint32_t v = g_hist[i];
    sh[t] = v;
    __syncthreads();
    #pragma unroll
    for (int off = 1; off < 1024; off <<= 1) {
        uint32_t u = (t >= off) ? sh[t - off] : 0u;
        __syncthreads();
        sh[t] += u;
        __syncthreads();
    }
    g_hist[i] = sh[t] - v;
    if (t == 1023) g_bsum[blockIdx.x] = sh[t];
}

__global__ __launch_bounds__(128) void rgcn_scan_bsums()
{
    __shared__ uint32_t sh[128];
    int t = threadIdx.x;
    uint32_t v = (t < NSCAN_BLK) ? g_bsum[t] : 0u;
    sh[t] = v;
    __syncthreads();
    #pragma unroll
    for (int off = 1; off < 128; off <<= 1) {
        uint32_t u = (t >= off) ? sh[t - off] : 0u;
        __syncthreads();
        sh[t] += u;
        __syncthreads();
    }
    g_bsum[t] = sh[t] - v;
}

__global__ __launch_bounds__(1024) void rgcn_scan_add()
{
    int i = blockIdx.x * 1024 + threadIdx.x;
    g_hist[i] += g_bsum[blockIdx.x];
}

__global__ void rgcn_scatter_kernel(
    const int*   __restrict__ r,
    const float* __restrict__ norm,
    const int*   __restrict__ src,
    const int*   __restrict__ dst,
    int n_edges)
{
    int e = blockIdx.x * blockDim.x + threadIdx.x;
    if (e >= n_edges) return;
    uint32_t pos = atomicAdd(&g_hist[(unsigned)dst[e]], 1u);
    uint2 ed;
    ed.x = (unsigned)src[e] | ((unsigned)r[e] << 20);
    ed.y = __float_as_uint(norm[e]);
    g_edges2[pos] = ed;
}

// ---------------------------------------------------------------------------
// Edge aggregate: one warp per dst node; HALF-WARP per edge (uint4 = 8 dims
// per lane). One x-load instruction covers 2 edges; unroll-2 => 4 edges in
// flight per warp. Final shfl_xor(16) combines the two half-warp partials.
// ---------------------------------------------------------------------------
__device__ __forceinline__ void agg8(float a[4][8], uint2 ed, uint4 qv,
                                     const float* __restrict__ w_comp)
{
    float4 cc = __ldg(reinterpret_cast<const float4*>(w_comp) + (ed.x >> 20));
    float nm  = __uint_as_float(ed.y);
    float c[4] = { nm * cc.x, nm * cc.y, nm * cc.z, nm * cc.w };
    float2 x01 = __half22float2(*reinterpret_cast<__half2*>(&qv.x));
    float2 x23 = __half22float2(*reinterpret_cast<__half2*>(&qv.y));
    float2 x45 = __half22float2(*reinterpret_cast<__half2*>(&qv.z));
    float2 x67 = __half22float2(*reinterpret_cast<__half2*>(&qv.w));
    #pragma unroll
    for (int b = 0; b < 4; ++b) {
        a[b][0] += c[b] * x01.x; a[b][1] += c[b] * x01.y;
        a[b][2] += c[b] * x23.x; a[b][3] += c[b] * x23.y;
        a[b][4] += c[b] * x45.x; a[b][5] += c[b] * x45.y;
        a[b][6] += c[b] * x67.x; a[b][7] += c[b] * x67.y;
    }
}

__global__ __launch_bounds__(256) void rgcn_edge_agg(
    const float* __restrict__ w_comp,
    int n_nodes)
{
    int d    = blockIdx.x * 8 + (threadIdx.x >> 5);
    int lane = threadIdx.x & 31;
    if (d >= n_nodes) return;

    const int hw = lane >> 4;      // which edge of the pair this lane serves
    const int ll = lane & 15;      // dim-quad within the row (8 dims)

    uint32_t end   = __ldg(&g_hist[d]);
    uint32_t begin = (d > 0) ? __ldg(&g_hist[d - 1]) : 0u;

    float a[4][8];
    #pragma unroll
    for (int b = 0; b < 4; ++b)
        #pragma unroll
        for (int j = 0; j < 8; ++j) a[b][j] = 0.f;

    uint32_t e = begin;
    // main loop: 4 edges per iteration (2 loads in flight x 2 edges per load)
    for (; e + 4 <= end; e += 4) {
        uint2 ed0 = __ldg(&g_edges2[e + hw]);
        uint2 ed1 = __ldg(&g_edges2[e + 2 + hw]);
        uint4 q0 = __ldg(reinterpret_cast<const uint4*>(
                        g_x + (size_t)(ed0.x & 0xFFFFFu) * DHID) + ll);
        uint4 q1 = __ldg(reinterpret_cast<const uint4*>(
                        g_x + (size_t)(ed1.x & 0xFFFFFu) * DHID) + ll);
        agg8(a, ed0, q0, w_comp);
        agg8(a, ed1, q1, w_comp);
    }
    // tail: 0-3 edges, 2 per iteration with predicated norm
    for (; e < end; e += 2) {
        uint32_t idx = e + hw;
        uint2 ed = __ldg(&g_edges2[(idx < end) ? idx : (end - 1)]);
        if (idx >= end) ed.y = 0u;   // norm = 0 -> zero contribution
        uint4 q = __ldg(reinterpret_cast<const uint4*>(
                       g_x + (size_t)(ed.x & 0xFFFFFu) * DHID) + ll);
        agg8(a, ed, q, w_comp);
    }

    // combine the two half-warp partials (same dims live at lane ^ 16)
    #pragma unroll
    for (int b = 0; b < 4; ++b)
        #pragma unroll
        for (int j = 0; j < 8; ++j)
            a[b][j] += __shfl_xor_sync(0xffffffffu, a[b][j], 16);

    uint32_t deg = end - begin;
    float rc = (deg > 0u) ? (1.0f / (float)deg) : 1.0f;

    // store: lane (hw,ll) writes bases {2*hw, 2*hw+1}, dims [8*ll, 8*ll+8)
    __half* yrow = g_y + (size_t)d * (NB * DHID);
    #pragma unroll
    for (int b2 = 0; b2 < 2; ++b2) {
        int b = hw * 2 + b2;
        __half2 p0 = __floats2half2_rn(a[b][0] * rc, a[b][1] * rc);
        __half2 p1 = __floats2half2_rn(a[b][2] * rc, a[b][3] * rc);
        __half2 p2 = __floats2half2_rn(a[b][4] * rc, a[b][5] * rc);
        __half2 p3 = __floats2half2_rn(a[b][6] * rc, a[b][7] * rc);
        uint4 pk;
        pk.x = *reinterpret_cast<uint32_t*>(&p0);
        pk.y = *reinterpret_cast<uint32_t*>(&p1);
        pk.z = *reinterpret_cast<uint32_t*>(&p2);
        pk.w = *reinterpret_cast<uint32_t*>(&p3);
        *reinterpret_cast<uint4*>(yrow + b * DHID + ll * 8) = pk;
    }
}

// ---------------------------------------------------------------------------
// HMMA helpers
// ---------------------------------------------------------------------------
__device__ __forceinline__ uint32_t smem_u32(const void* p) {
    uint32_t a;
    asm("{ .reg .u64 t; cvta.to.shared.u64 t, %1; cvt.u32.u64 %0, t; }" : "=r"(a) : "l"(p));
    return a;
}
__device__ __forceinline__ void ldsm_x4(uint32_t* r, uint32_t addr) {
    asm volatile("ldmatrix.sync.aligned.m8n8.x4.shared.b16 {%0,%1,%2,%3}, [%4];"
                 : "=r"(r[0]), "=r"(r[1]), "=r"(r[2]), "=r"(r[3]) : "r"(addr));
}
__device__ __forceinline__ void ldsm_x2(uint32_t* r, uint32_t addr) {
    asm volatile("ldmatrix.sync.aligned.m8n8.x2.shared.b16 {%0,%1}, [%2];"
                 : "=r"(r[0]), "=r"(r[1]) : "r"(addr));
}
__device__ __forceinline__ void mma16816(float* c, const uint32_t* a, const uint32_t* b) {
    asm volatile(
        "mma.sync.aligned.m16n8k16.row.col.f32.f16.f16.f32 "
        "{%0,%1,%2,%3}, {%4,%5,%6,%7}, {%8,%9}, {%0,%1,%2,%3};"
        : "+f"(c[0]), "+f"(c[1]), "+f"(c[2]), "+f"(c[3])
        : "r"(a[0]), "r"(a[1]), "r"(a[2]), "r"(a[3]), "r"(b[0]), "r"(b[1]));
}

// ---------------------------------------------------------------------------
// GEMM2: EXACT R12 version (64-row M tiles, double-buffered cp.async).
// ---------------------------------------------------------------------------
#define STAGE_A (64 * KP)
#define STAGE_B (128 * KP)
#define SMEM_BYTES2 ((2 * STAGE_A + 2 * STAGE_B) * 2)

__global__ __launch_bounds__(256) void rgcn_gemm2(
    const float* __restrict__ bias,
    float*       __restrict__ out,
    int n_nodes)
{
    extern __shared__ __align__(16) __half smem[];
    __half* Abuf[2] = { smem, smem + STAGE_A };
    __half* Bbuf[2] = { smem + 2 * STAGE_A, smem + 2 * STAGE_A + STAGE_B };

    const int tid  = threadIdx.x;
    const int lane = tid & 31;
    const int wrp  = tid >> 5;
    const int wm   = (wrp & 1) * 32;
    const int wn   = (wrp >> 1) * 32;
    const int m0   = blockIdx.x * 64;

    const int arow  = (lane & 15);
    const int acol8 = 8 * (lane >> 4);
    const int brow  = (lane & 7);
    const int bcol8 = 8 * ((lane >> 3) & 1);
    const int gq = lane >> 2;
    const int tg = lane & 3;

    auto load_stage = [&](int kc, int st) {
        #pragma unroll
        for (int it = 0; it < 4; ++it) {
            int idx = it * 256 + tid;
            int m   = idx >> 4;
            int kq  = (idx & 15) * 8;
            int row = m0 + m;
            int rcl = (row < n_nodes) ? row : (n_nodes - 1);
            const __half* gp = g_y + (size_t)rcl * (NB * DHID) + kc * DHID + kq;
            uint32_t sa = smem_u32(Abuf[st] + m * KP + kq);
            unsigned sz = (row < n_nodes) ? 16u : 0u;
            asm volatile("cp.async.cg.shared.global [%0], [%1], 16, %2;"
                         :: "r"(sa), "l"(gp), "r"(sz));
        }
        #pragma unroll
        for (int it = 0; it < 8; ++it) {
            int idx = it * 256 + tid;
            int o   = idx >> 4;
            int kq  = (idx & 15) * 8;
            const __half* gp = g_wt2 + o * (NB * DHID) + kc * DHID + kq;
            uint32_t sa = smem_u32(Bbuf[st] + o * KP + kq);
            asm volatile("cp.async.cg.shared.global [%0], [%1], 16;"
                         :: "r"(sa), "l"(gp));
        }
        asm volatile("cp.async.commit_group;" ::: "memory");
    };

    float acc[2][4][4];
    #pragma unroll
    for (int mi = 0; mi < 2; ++mi)
        #pragma unroll
        for (int ni = 0; ni < 4; ++ni)
            #pragma unroll
            for (int q = 0; q < 4; ++q) acc[mi][ni][q] = 0.f;

    load_stage(0, 0);

    for (int kc = 0; kc < 4; ++kc) {
        asm volatile("cp.async.wait_group 0;" ::: "memory");
        __syncthreads();

        if (kc + 1 < 4) load_stage(kc + 1, (kc + 1) & 1);

        int st = kc & 1;
        uint32_t as_b = smem_u32(Abuf[st]);
        uint32_t bs_b = smem_u32(Bbuf[st]);

        #pragma unroll
        for (int kk = 0; kk < 8; ++kk) {
            uint32_t af[2][4], bf[4][2];
            #pragma unroll
            for (int mi = 0; mi < 2; ++mi)
                ldsm_x4(af[mi], as_b + ((wm + mi * 16 + arow) * KP + kk * 16 + acol8) * 2);
            #pragma unroll
            for (int ni = 0; ni < 4; ++ni)
                ldsm_x2(bf[ni], bs_b + ((wn + ni * 8 + brow) * KP + kk * 16 + bcol8) * 2);
            #pragma unroll
            for (int mi = 0; mi < 2; ++mi)
                #pragma unroll
                for (int ni = 0; ni < 4; ++ni)
                    mma16816(acc[mi][ni], af[mi], bf[ni]);
        }
        __syncthreads();
    }

    #pragma unroll
    for (int mi = 0; mi < 2; ++mi) {
        #pragma unroll
        for (int half_ = 0; half_ < 2; ++half_) {
            int row = m0 + wm + mi * 16 + gq + half_ * 8;
            if (row < n_nodes) {
                #pragma unroll
                for (int ni = 0; ni < 4; ++ni) {
                    int col = wn + ni * 8 + tg * 2;
                    float2 bv = __ldg(reinterpret_cast<const float2*>(bias) + (col >> 1));
                    float2 o;
                    o.x = acc[mi][ni][half_ * 2]     + bv.x;
                    o.y = acc[mi][ni][half_ * 2 + 1] + bv.y;
                    *reinterpret_cast<float2*>(out + (size_t)row * DHID + col) = o;
                }
            }
        }
    }
}

// ---------------------------------------------------------------------------
// Inputs: h, r, norm, src, dst, emb_table, weight, w_comp, h_bias
// ---------------------------------------------------------------------------
extern "C" void kernel_launch(void* const* d_in, const int* in_sizes, int n_in,
                              void* d_out, int out_size)
{
    const int*   h      = (const int*)  d_in[0];
    const int*   r      = (const int*)  d_in[1];
    const float* norm   = (const float*)d_in[2];
    const int*   src    = (const int*)  d_in[3];
    const int*   dst    = (const int*)  d_in[4];
    const float* emb    = (const float*)d_in[5];
    const float* weight = (const float*)d_in[6];
    const float* w_comp = (const float*)d_in[7];
    const float* bias   = (const float*)d_in[8];

    int n_nodes = in_sizes[0];
    int n_edges = in_sizes[1];
    float* out = (float*)d_out;

    cudaFuncSetAttribute(rgcn_gemm2, cudaFuncAttributeMaxDynamicSharedMemorySize, SMEM_BYTES2);

    // fused preps (R12 exact)
    int prep_threads = n_nodes * 32;
    rgcn_prep_all<<<(prep_threads + 255) / 256, 256>>>(weight, h, emb, n_nodes);

    // dst counting sort (R12 exact)
    int eblk = (n_edges + 255) / 256;
    rgcn_hist_kernel<<<eblk, 256>>>(dst, n_edges);
    rgcn_scan_local<<<NSCAN_BLK, 1024>>>();
    rgcn_scan_bsums<<<1, 128>>>();
    rgcn_scan_add<<<NSCAN_BLK, 1024>>>();
    rgcn_scatter_kernel<<<eblk, 256>>>(r, norm, src, dst, n_edges);

    // per-dst aggregation (half-warp per edge: 4 edges in flight per warp)
    rgcn_edge_agg<<<(n_nodes + 7) / 8, 256>>>(w_comp, n_nodes);

    // projection GEMM + bias (R12 exact)
    rgcn_gemm2<<<(n_nodes + 63) / 64, 256, SMEM_BYTES2>>>(bias, out, n_nodes);
}

// round 16
// speedup vs baseline: 1.2633x; 1.2633x over previous
#include <cuda_runtime.h>
#include <cuda_fp16.h>
#include <cstdint>

#define DHID   128
#define NB     4
#define NN_MAX 100096
#define NE_MAX 800000
#define NBKT_N 102400
#define NSCAN_BLK (NBKT_N / 1024)

// Scratch
__device__ __half   g_x[(size_t)NN_MAX * DHID];         // fp16 node feats (25.6 MB)
__device__ __half   g_y[(size_t)NN_MAX * NB * DHID];    // fp16 aggregated, deg-scaled (102 MB)
__device__ __half   g_wt2[DHID * NB * DHID];            // Wt[o][b*128+i] fp16
__device__ uint32_t g_hist[NBKT_N];
__device__ uint32_t g_bsum[128];
__device__ uint2    g_edges2[NE_MAX];                   // dst-sorted {src|rel<<20, norm}

#define KP 136

// ---------------------------------------------------------------------------
// Fused prep: weight transpose + x fp16 conversion + hist zero (R12 exact)
// ---------------------------------------------------------------------------
__global__ void rgcn_prep_all(const float* __restrict__ weight,
                              const int*   __restrict__ h,
                              const float* __restrict__ emb,
                              int n_nodes)
{
    int idx = blockIdx.x * blockDim.x + threadIdx.x;

    if (idx < NB * DHID * DHID) {
        int b = idx >> 14;
        int i = (idx >> 7) & 127;
        int o = idx & 127;
        g_wt2[o * (NB * DHID) + b * DHID + i] = __float2half_rn(weight[idx]);
    }
    if (idx < NBKT_N) g_hist[idx] = 0u;

    if (idx < n_nodes * 32) {
        int n  = idx >> 5;
        int qc = (idx & 31) * 4;
        int hn = __ldg(h + n);
        float4 v = *reinterpret_cast<const float4*>(emb + (size_t)hn * DHID + qc);
        __half2 p0 = __floats2half2_rn(v.x, v.y);
        __half2 p1 = __floats2half2_rn(v.z, v.w);
        uint2 pk;
        pk.x = *reinterpret_cast<uint32_t*>(&p0);
        pk.y = *reinterpret_cast<uint32_t*>(&p1);
        *reinterpret_cast<uint2*>(g_x + (size_t)n * DHID + qc) = pk;
    }
}

// ---------------------------------------------------------------------------
// dst counting sort: scalar hist (R12 exact)
// ---------------------------------------------------------------------------
__global__ void rgcn_hist_kernel(const int* __restrict__ dst, int n_edges)
{
    int e = blockIdx.x * blockDim.x + threadIdx.x;
    if (e >= n_edges) return;
    atomicAdd(&g_hist[(unsigned)dst[e]], 1u);
}

__global__ __launch_bounds__(1024) void rgcn_scan_local()
{
    __shared__ uint32_t sh[1024];
    int t = threadIdx.x;
    int i = blockIdx.x * 1024 + t;
    uint32_t v = g_hist[i];
    sh[t] = v;
    __syncthreads();
    #pragma unroll
    for (int off = 1; off < 1024; off <<= 1) {
        uint32_t u = (t >= off) ? sh[t - off] : 0u;
        __syncthreads();
        sh[t] += u;
        __syncthreads();
    }
    g_hist[i] = sh[t] - v;
    if (t == 1023) g_bsum[blockIdx.x] = sh[t];
}

// scan_add with fused block-sum prefix (saves the scan_bsums launch).
__global__ __launch_bounds__(1024) void rgcn_scan_add()
{
    __shared__ uint32_t soff;
    int t = threadIdx.x;
    if (t < 32) {
        uint32_t s = 0;
        #pragma unroll
        for (int j = 0; j < 4; ++j) {
            int idx = t + j * 32;
            if (idx < blockIdx.x && idx < NSCAN_BLK) s += g_bsum[idx];
        }
        #pragma unroll
        for (int o = 16; o > 0; o >>= 1) s += __shfl_down_sync(0xffffffffu, s, o);
        if (t == 0) soff = s;
    }
    __syncthreads();
    int i = blockIdx.x * 1024 + t;
    g_hist[i] += soff;
}

__global__ void rgcn_scatter_kernel(
    const int*   __restrict__ r,
    const float* __restrict__ norm,
    const int*   __restrict__ src,
    const int*   __restrict__ dst,
    int n_edges)
{
    int e = blockIdx.x * blockDim.x + threadIdx.x;
    if (e >= n_edges) return;
    uint32_t pos = atomicAdd(&g_hist[(unsigned)dst[e]], 1u);
    uint2 ed;
    ed.x = (unsigned)src[e] | ((unsigned)r[e] << 20);
    ed.y = __float_as_uint(norm[e]);
    g_edges2[pos] = ed;
}

// ---------------------------------------------------------------------------
// Edge aggregate: EXACT R9/R12 version (one warp per dst, unroll-2). Frozen.
// ---------------------------------------------------------------------------
__global__ __launch_bounds__(256) void rgcn_edge_agg(
    const float* __restrict__ w_comp,
    int n_nodes)
{
    int d    = blockIdx.x * 8 + (threadIdx.x >> 5);
    int lane = threadIdx.x & 31;
    if (d >= n_nodes) return;

    uint32_t end   = __ldg(&g_hist[d]);
    uint32_t begin = (d > 0) ? __ldg(&g_hist[d - 1]) : 0u;

    float a0x = 0.f, a0y = 0.f, a0z = 0.f, a0w = 0.f;
    float a1x = 0.f, a1y = 0.f, a1z = 0.f, a1w = 0.f;
    float a2x = 0.f, a2y = 0.f, a2z = 0.f, a2w = 0.f;
    float a3x = 0.f, a3y = 0.f, a3z = 0.f, a3w = 0.f;

    uint32_t e = begin;
    for (; e + 2 <= end; e += 2) {
        uint2 ed0 = __ldg(&g_edges2[e]);
        uint2 ed1 = __ldg(&g_edges2[e + 1]);
        int   s0 = (int)(ed0.x & 0xFFFFFu), s1 = (int)(ed1.x & 0xFFFFFu);
        uint2 q0 = __ldg(reinterpret_cast<const uint2*>(g_x + (size_t)s0 * DHID) + lane);
        uint2 q1 = __ldg(reinterpret_cast<const uint2*>(g_x + (size_t)s1 * DHID) + lane);
        float4 cc0 = __ldg(reinterpret_cast<const float4*>(w_comp) + (ed0.x >> 20));
        float4 cc1 = __ldg(reinterpret_cast<const float4*>(w_comp) + (ed1.x >> 20));
        float nm0 = __uint_as_float(ed0.y), nm1 = __uint_as_float(ed1.y);

        {
            float c0 = nm0 * cc0.x, c1 = nm0 * cc0.y, c2 = nm0 * cc0.z, c3 = nm0 * cc0.w;
            float2 x01 = __half22float2(*reinterpret_cast<__half2*>(&q0.x));
            float2 x23 = __half22float2(*reinterpret_cast<__half2*>(&q0.y));
            a0x += c0 * x01.x; a0y += c0 * x01.y; a0z += c0 * x23.x; a0w += c0 * x23.y;
            a1x += c1 * x01.x; a1y += c1 * x01.y; a1z += c1 * x23.x; a1w += c1 * x23.y;
            a2x += c2 * x01.x; a2y += c2 * x01.y; a2z += c2 * x23.x; a2w += c2 * x23.y;
            a3x += c3 * x01.x; a3y += c3 * x01.y; a3z += c3 * x23.x; a3w += c3 * x23.y;
        }
        {
            float c0 = nm1 * cc1.x, c1 = nm1 * cc1.y, c2 = nm1 * cc1.z, c3 = nm1 * cc1.w;
            float2 x01 = __half22float2(*reinterpret_cast<__half2*>(&q1.x));
            float2 x23 = __half22float2(*reinterpret_cast<__half2*>(&q1.y));
            a0x += c0 * x01.x; a0y += c0 * x01.y; a0z += c0 * x23.x; a0w += c0 * x23.y;
            a1x += c1 * x01.x; a1y += c1 * x01.y; a1z += c1 * x23.x; a1w += c1 * x23.y;
            a2x += c2 * x01.x; a2y += c2 * x01.y; a2z += c2 * x23.x; a2w += c2 * x23.y;
            a3x += c3 * x01.x; a3y += c3 * x01.y; a3z += c3 * x23.x; a3w += c3 * x23.y;
        }
    }
    if (e < end) {
        uint2 ed = __ldg(&g_edges2[e]);
        int   s  = (int)(ed.x & 0xFFFFFu);
        uint2 q  = __ldg(reinterpret_cast<const uint2*>(g_x + (size_t)s * DHID) + lane);
        float4 cc = __ldg(reinterpret_cast<const float4*>(w_comp) + (ed.x >> 20));
        float nm = __uint_as_float(ed.y);
        float c0 = nm * cc.x, c1 = nm * cc.y, c2 = nm * cc.z, c3 = nm * cc.w;
        float2 x01 = __half22float2(*reinterpret_cast<__half2*>(&q.x));
        float2 x23 = __half22float2(*reinterpret_cast<__half2*>(&q.y));
        a0x += c0 * x01.x; a0y += c0 * x01.y; a0z += c0 * x23.x; a0w += c0 * x23.y;
        a1x += c1 * x01.x; a1y += c1 * x01.y; a1z += c1 * x23.x; a1w += c1 * x23.y;
        a2x += c2 * x01.x; a2y += c2 * x01.y; a2z += c2 * x23.x; a2w += c2 * x23.y;
        a3x += c3 * x01.x; a3y += c3 * x01.y; a3z += c3 * x23.x; a3w += c3 * x23.y;
    }

    uint32_t deg = end - begin;
    float rc = (deg > 0u) ? (1.0f / (float)deg) : 1.0f;

    __half* yrow = g_y + (size_t)d * (NB * DHID) + lane * 4;
    {
        __half2 p0 = __floats2half2_rn(a0x * rc, a0y * rc);
        __half2 p1 = __floats2half2_rn(a0z * rc, a0w * rc);
        uint2 pk = {*reinterpret_cast<uint32_t*>(&p0), *reinterpret_cast<uint32_t*>(&p1)};
        *reinterpret_cast<uint2*>(yrow) = pk;
    }
    {
        __half2 p0 = __floats2half2_rn(a1x * rc, a1y * rc);
        __half2 p1 = __floats2half2_rn(a1z * rc, a1w * rc);
        uint2 pk = {*reinterpret_cast<uint32_t*>(&p0), *reinterpret_cast<uint32_t*>(&p1)};
        *reinterpret_cast<uint2*>(yrow + DHID) = pk;
    }
    {
        __half2 p0 = __floats2half2_rn(a2x * rc, a2y * rc);
        __half2 p1 = __floats2half2_rn(a2z * rc, a2w * rc);
        uint2 pk = {*reinterpret_cast<uint32_t*>(&p0), *reinterpret_cast<uint32_t*>(&p1)};
        *reinterpret_cast<uint2*>(yrow + 2 * DHID) = pk;
    }
    {
        __half2 p0 = __floats2half2_rn(a3x * rc, a3y * rc);
        __half2 p1 = __floats2half2_rn(a3z * rc, a3w * rc);
        uint2 pk = {*reinterpret_cast<uint32_t*>(&p0), *reinterpret_cast<uint32_t*>(&p1)};
        *reinterpret_cast<uint2*>(yrow + 3 * DHID) = pk;
    }
}

// ---------------------------------------------------------------------------
// HMMA helpers
// ---------------------------------------------------------------------------
__device__ __forceinline__ uint32_t smem_u32(const void* p) {
    uint32_t a;
    asm("{ .reg .u64 t; cvta.to.shared.u64 t, %1; cvt.u32.u64 %0, t; }" : "=r"(a) : "l"(p));
    return a;
}
__device__ __forceinline__ void ldsm_x4(uint32_t* r, uint32_t addr) {
    asm volatile("ldmatrix.sync.aligned.m8n8.x4.shared.b16 {%0,%1,%2,%3}, [%4];"
                 : "=r"(r[0]), "=r"(r[1]), "=r"(r[2]), "=r"(r[3]) : "r"(addr));
}
__device__ __forceinline__ void ldsm_x2(uint32_t* r, uint32_t addr) {
    asm volatile("ldmatrix.sync.aligned.m8n8.x2.shared.b16 {%0,%1}, [%2];"
                 : "=r"(r[0]), "=r"(r[1]) : "r"(addr));
}
__device__ __forceinline__ void mma16816(float* c, const uint32_t* a, const uint32_t* b) {
    asm volatile(
        "mma.sync.aligned.m16n8k16.row.col.f32.f16.f16.f32 "
        "{%0,%1,%2,%3}, {%4,%5,%6,%7}, {%8,%9}, {%0,%1,%2,%3};"
        : "+f"(c[0]), "+f"(c[1]), "+f"(c[2]), "+f"(c[3])
        : "r"(a[0]), "r"(a[1]), "r"(a[2]), "r"(a[3]), "r"(b[0]), "r"(b[1]));
}

// ---------------------------------------------------------------------------
// GEMM2: EXACT R12 version (64-row M tiles, double-buffered cp.async).
// ---------------------------------------------------------------------------
#define STAGE_A (64 * KP)
#define STAGE_B (128 * KP)
#define SMEM_BYTES2 ((2 * STAGE_A + 2 * STAGE_B) * 2)

__global__ __launch_bounds__(256) void rgcn_gemm2(
    const float* __restrict__ bias,
    float*       __restrict__ out,
    int n_nodes)
{
    extern __shared__ __align__(16) __half smem[];
    __half* Abuf[2] = { smem, smem + STAGE_A };
    __half* Bbuf[2] = { smem + 2 * STAGE_A, smem + 2 * STAGE_A + STAGE_B };

    const int tid  = threadIdx.x;
    const int lane = tid & 31;
    const int wrp  = tid >> 5;
    const int wm   = (wrp & 1) * 32;
    const int wn   = (wrp >> 1) * 32;
    const int m0   = blockIdx.x * 64;

    const int arow  = (lane & 15);
    const int acol8 = 8 * (lane >> 4);
    const int brow  = (lane & 7);
    const int bcol8 = 8 * ((lane >> 3) & 1);
    const int gq = lane >> 2;
    const int tg = lane & 3;

    auto load_stage = [&](int kc, int st) {
        #pragma unroll
        for (int it = 0; it < 4; ++it) {
            int idx = it * 256 + tid;
            int m   = idx >> 4;
            int kq  = (idx & 15) * 8;
            int row = m0 + m;
            int rcl = (row < n_nodes) ? row : (n_nodes - 1);
            const __half* gp = g_y + (size_t)rcl * (NB * DHID) + kc * DHID + kq;
            uint32_t sa = smem_u32(Abuf[st] + m * KP + kq);
            unsigned sz = (row < n_nodes) ? 16u : 0u;
            asm volatile("cp.async.cg.shared.global [%0], [%1], 16, %2;"
                         :: "r"(sa), "l"(gp), "r"(sz));
        }
        #pragma unroll
        for (int it = 0; it < 8; ++it) {
            int idx = it * 256 + tid;
            int o   = idx >> 4;
            int kq  = (idx & 15) * 8;
            const __half* gp = g_wt2 + o * (NB * DHID) + kc * DHID + kq;
            uint32_t sa = smem_u32(Bbuf[st] + o * KP + kq);
            asm volatile("cp.async.cg.shared.global [%0], [%1], 16;"
                         :: "r"(sa), "l"(gp));
        }
        asm volatile("cp.async.commit_group;" ::: "memory");
    };

    float acc[2][4][4];
    #pragma unroll
    for (int mi = 0; mi < 2; ++mi)
        #pragma unroll
        for (int ni = 0; ni < 4; ++ni)
            #pragma unroll
            for (int q = 0; q < 4; ++q) acc[mi][ni][q] = 0.f;

    load_stage(0, 0);

    for (int kc = 0; kc < 4; ++kc) {
        asm volatile("cp.async.wait_group 0;" ::: "memory");
        __syncthreads();

        if (kc + 1 < 4) load_stage(kc + 1, (kc + 1) & 1);

        int st = kc & 1;
        uint32_t as_b = smem_u32(Abuf[st]);
        uint32_t bs_b = smem_u32(Bbuf[st]);

        #pragma unroll
        for (int kk = 0; kk < 8; ++kk) {
            uint32_t af[2][4], bf[4][2];
            #pragma unroll
            for (int mi = 0; mi < 2; ++mi)
                ldsm_x4(af[mi], as_b + ((wm + mi * 16 + arow) * KP + kk * 16 + acol8) * 2);
            #pragma unroll
            for (int ni = 0; ni < 4; ++ni)
                ldsm_x2(bf[ni], bs_b + ((wn + ni * 8 + brow) * KP + kk * 16 + bcol8) * 2);
            #pragma unroll
            for (int mi = 0; mi < 2; ++mi)
                #pragma unroll
                for (int ni = 0; ni < 4; ++ni)
                    mma16816(acc[mi][ni], af[mi], bf[ni]);
        }
        __syncthreads();
    }

    #pragma unroll
    for (int mi = 0; mi < 2; ++mi) {
        #pragma unroll
        for (int half_ = 0; half_ < 2; ++half_) {
            int row = m0 + wm + mi * 16 + gq + half_ * 8;
            if (row < n_nodes) {
                #pragma unroll
                for (int ni = 0; ni < 4; ++ni) {
                    int col = wn + ni * 8 + tg * 2;
                    float2 bv = __ldg(reinterpret_cast<const float2*>(bias) + (col >> 1));
                    float2 o;
                    o.x = acc[mi][ni][half_ * 2]     + bv.x;
                    o.y = acc[mi][ni][half_ * 2 + 1] + bv.y;
                    *reinterpret_cast<float2*>(out + (size_t)row * DHID + col) = o;
                }
            }
        }
    }
}

// ---------------------------------------------------------------------------
// Inputs: h, r, norm, src, dst, emb_table, weight, w_comp, h_bias
// ---------------------------------------------------------------------------
extern "C" void kernel_launch(void* const* d_in, const int* in_sizes, int n_in,
                              void* d_out, int out_size)
{
    const int*   h      = (const int*)  d_in[0];
    const int*   r      = (const int*)  d_in[1];
    const float* norm   = (const float*)d_in[2];
    const int*   src    = (const int*)  d_in[3];
    const int*   dst    = (const int*)  d_in[4];
    const float* emb    = (const float*)d_in[5];
    const float* weight = (const float*)d_in[6];
    const float* w_comp = (const float*)d_in[7];
    const float* bias   = (const float*)d_in[8];

    int n_nodes = in_sizes[0];
    int n_edges = in_sizes[1];
    float* out = (float*)d_out;

    cudaFuncSetAttribute(rgcn_gemm2, cudaFuncAttributeMaxDynamicSharedMemorySize, SMEM_BYTES2);

    // fused preps (R12 exact)
    int prep_threads = n_nodes * 32;
    rgcn_prep_all<<<(prep_threads + 255) / 256, 256>>>(weight, h, emb, n_nodes);

    // dst counting sort (scalar hist; scan_bsums folded into scan_add)
    int eblk = (n_edges + 255) / 256;
    rgcn_hist_kernel<<<eblk, 256>>>(dst, n_edges);
    rgcn_scan_local<<<NSCAN_BLK, 1024>>>();
    rgcn_scan_add<<<NSCAN_BLK, 1024>>>();
    rgcn_scatter_kernel<<<eblk, 256>>>(r, norm, src, dst, n_edges);

    // per-dst aggregation (R9/R12 exact, frozen)
    rgcn_edge_agg<<<(n_nodes + 7) / 8, 256>>>(w_comp, n_nodes);

    // projection GEMM + bias (R12 exact)
    rgcn_gemm2<<<(n_nodes + 63) / 64, 256, SMEM_BYTES2>>>(bias, out, n_nodes);
}